// round 4
// baseline (speedup 1.0000x reference)
#include <cuda_runtime.h>
#include <math.h>

// ---------------------------------------------------------------------------
// f32x2 packed-math helpers (FFMA2 — only reachable via PTX fma.rn.f32x2)
// ---------------------------------------------------------------------------
typedef unsigned long long ull;

__device__ __forceinline__ ull pack2(float lo, float hi) {
    ull r; asm("mov.b64 %0,{%1,%2};" : "=l"(r) : "f"(lo), "f"(hi)); return r;
}
__device__ __forceinline__ float2 unpack2(ull v) {
    float2 r; asm("mov.b64 {%0,%1},%2;" : "=f"(r.x), "=f"(r.y) : "l"(v)); return r;
}
__device__ __forceinline__ void ffma2(ull& d, ull a, ull b) {
    asm("fma.rn.f32x2 %0,%1,%2,%3;" : "=l"(d) : "l"(a), "l"(b), "l"(d));
}

// ---------------------------------------------------------------------------
// Static scratch (no allocations allowed)
// ---------------------------------------------------------------------------
__device__ float g_buf1[2048 * 32 * 15 * 15];   // conv1 out
__device__ float g_buf2[2048 * 64 * 6 * 6];     // conv2 out
__device__ float g_buf3[2048 * 1024];           // conv3 out / flatten
__device__ float g_feats[2048 * 512];           // fc out
__device__ float g_gatesx[2048 * 1024];         // f_t @ w_ih^T + b_ih + b_hh
__device__ float g_hbuf[2][32 * 256];           // LSTM h ping-pong
__device__ unsigned g_count;                    // grid barrier
__device__ unsigned g_gen;

#define SMEM1 ((4 * 64 * 68 + 32 * 260) * 4)
#define SMEM2 ((2 * 7680 + 64 * 132) * 4)
#define SMEM3 ((9216 + 32 * 577) * 4)
#define SMEML ((16 * 264 + 32 * 264 + 512 + 128) * 4)

// ---------------------------------------------------------------------------
// conv1: in (n,4,64,64)/255 -> relu -> out (n,32,15,15), k=8 s=4
// block = one image, 192 threads (180 active). Thread tile 8(oc) x 5(ow),
// f32x2 k-packed along kw (kw contiguous -> free pairs, no splats).
// img rows padded to 68 floats for bank spread.
// ---------------------------------------------------------------------------
__global__ __launch_bounds__(192, 2)
void conv1_kernel(const float* __restrict__ x, const float* __restrict__ w,
                  const float* __restrict__ bias, float* __restrict__ out)
{
    extern __shared__ __align__(16) float sm[];
    float* img = sm;              // 4 * 64 * 68
    float* wts = sm + 4 * 64 * 68;  // 32 rows, stride 260

    const int tid = threadIdx.x;
    const int n = blockIdx.x;

    const float4* xin = (const float4*)(x + (size_t)n * 16384);
    const float inv255 = 1.0f / 255.0f;
    for (int i = tid; i < 4096; i += 192) {
        const int c = i >> 10;
        const int r = (i >> 4) & 63;
        const int c4 = (i & 15) * 4;
        float4 v = xin[i];
        v.x *= inv255; v.y *= inv255; v.z *= inv255; v.w *= inv255;
        *(float4*)(img + c * 4352 + r * 68 + c4) = v;
    }
    for (int i = tid; i < 8192; i += 192) {
        const int oc = i >> 8, r = i & 255;
        wts[oc * 260 + r] = w[i];
    }
    __syncthreads();

    if (tid < 180) {
        const int oh  = tid / 12;
        const int r   = tid % 12;
        const int ocg = r & 3;
        const int owg = r >> 2;
        const int oc0 = ocg * 8, ow0 = owg * 5;

        ull acc[8][5];
        #pragma unroll
        for (int i = 0; i < 8; i++)
            #pragma unroll
            for (int j = 0; j < 5; j++) acc[i][j] = 0ull;

        for (int c = 0; c < 4; c++) {
            const float* ib = img + c * 4352 + (oh * 4) * 68;
            const float* wb = wts + c * 64;
            #pragma unroll
            for (int kh = 0; kh < 8; kh++) {
                #pragma unroll
                for (int kwg = 0; kwg < 2; kwg++) {
                    ulonglong2 px[5];
                    #pragma unroll
                    for (int j = 0; j < 5; j++)
                        px[j] = *(const ulonglong2*)(ib + kh * 68 + (ow0 + j) * 4 + kwg * 4);
                    ulonglong2 pw[8];
                    #pragma unroll
                    for (int i = 0; i < 8; i++)
                        pw[i] = *(const ulonglong2*)(wb + (oc0 + i) * 260 + kh * 8 + kwg * 4);
                    #pragma unroll
                    for (int i = 0; i < 8; i++)
                        #pragma unroll
                        for (int j = 0; j < 5; j++) {
                            ffma2(acc[i][j], pw[i].x, px[j].x);
                            ffma2(acc[i][j], pw[i].y, px[j].y);
                        }
                }
            }
        }
        float* ob = out + (((size_t)n * 32 + oc0) * 15 + oh) * 15 + ow0;
        #pragma unroll
        for (int i = 0; i < 8; i++) {
            const float bi = bias[oc0 + i];
            #pragma unroll
            for (int j = 0; j < 5; j++) {
                const float2 s = unpack2(acc[i][j]);
                float v = s.x + s.y + bi;
                ob[i * 225 + j] = v > 0.0f ? v : 0.0f;
            }
        }
    }
}

// ---------------------------------------------------------------------------
// conv2: in (n,32,15,15) -> relu -> out (n,64,6,6), k=4 s=2
// block = 2 images, 192 threads. Thread tile 4(oc) x 6(ow) (full ow row),
// f32x2 k-packed along kw. img rows padded to 16 floats -> aligned pairs.
// Weights chunked 8 ic at a time.
// ---------------------------------------------------------------------------
__global__ __launch_bounds__(192, 2)
void conv2_kernel(const float* __restrict__ in, const float* __restrict__ w,
                  const float* __restrict__ bias, float* __restrict__ out)
{
    extern __shared__ __align__(16) float sm[];
    float* img = sm;            // 2 * 32*15*16 = 15360
    float* wk  = sm + 15360;    // 64 rows, stride 132 (8 ic * 16 per row)

    const int tid = threadIdx.x;
    const int nb = blockIdx.x * 2;

    for (int e = tid; e < 14400; e += 192) {
        const int im = e / 7200;
        const int rr = e - im * 7200;
        const int ic = rr / 225;
        const int r2 = rr - ic * 225;
        const int ih = r2 / 15;
        const int iw = r2 - ih * 15;
        img[im * 7680 + ic * 240 + ih * 16 + iw] = in[(size_t)(nb + im) * 7200 + rr];
    }

    const int im  = tid / 96;
    const int t   = tid % 96;
    const int ocg = t & 15;
    const int oh  = t >> 4;           // 0..5
    const int oc0 = ocg * 4;

    ull acc[4][6];
    #pragma unroll
    for (int i = 0; i < 4; i++)
        #pragma unroll
        for (int j = 0; j < 6; j++) acc[i][j] = 0ull;

    for (int icc = 0; icc < 4; icc++) {
        __syncthreads();
        for (int e = tid; e < 8192; e += 192) {
            const int oc = e >> 7, rr = e & 127;
            wk[oc * 132 + rr] = w[oc * 512 + icc * 128 + rr];
        }
        __syncthreads();

        #pragma unroll
        for (int ici = 0; ici < 8; ici++) {
            const float* ib = img + im * 7680 + (icc * 8 + ici) * 240 + (oh * 2) * 16;
            const float* wb = wk + ici * 16;
            #pragma unroll
            for (int kh = 0; kh < 4; kh++) {
                const ulonglong2 x01 = *(const ulonglong2*)(ib + kh * 16);
                const ulonglong2 x23 = *(const ulonglong2*)(ib + kh * 16 + 4);
                const ulonglong2 x45 = *(const ulonglong2*)(ib + kh * 16 + 8);
                const ulonglong2 x6_ = *(const ulonglong2*)(ib + kh * 16 + 12);
                const ull P[7] = {x01.x, x01.y, x23.x, x23.y, x45.x, x45.y, x6_.x};
                #pragma unroll
                for (int i = 0; i < 4; i++) {
                    const ulonglong2 wv = *(const ulonglong2*)(wb + (oc0 + i) * 132 + kh * 4);
                    #pragma unroll
                    for (int j = 0; j < 6; j++) {
                        ffma2(acc[i][j], wv.x, P[j]);
                        ffma2(acc[i][j], wv.y, P[j + 1]);
                    }
                }
            }
        }
    }
    const int n = nb + im;
    float* ob = out + (((size_t)n * 64 + oc0) * 6 + oh) * 6;
    #pragma unroll
    for (int i = 0; i < 4; i++) {
        const float bi = bias[oc0 + i];
        #pragma unroll
        for (int j = 0; j < 6; j++) {
            const float2 s = unpack2(acc[i][j]);
            float v = s.x + s.y + bi;
            ob[i * 36 + j] = v > 0.0f ? v : 0.0f;
        }
    }
}

// ---------------------------------------------------------------------------
// conv3: in (n,64,6,6) -> relu -> flatten out (n, 64*16), k=3 s=1 (unchanged)
// ---------------------------------------------------------------------------
__global__ __launch_bounds__(128, 2)
void conv3_kernel(const float* __restrict__ in, const float* __restrict__ w,
                  const float* __restrict__ bias, float* __restrict__ out)
{
    extern __shared__ float sm[];
    float* img = sm;            // 4 * 2304
    float* wk  = sm + 9216;     // 32 rows, stride 577

    const int tid = threadIdx.x;
    const int nbase = (blockIdx.x >> 1) * 4;
    const int oc0base = (blockIdx.x & 1) * 32;

    const float4* ip = (const float4*)(in + (size_t)nbase * 2304);
    for (int i = tid; i < 2304; i += 128) ((float4*)img)[i] = ip[i];
    for (int e = tid; e < 18432; e += 128) {
        int ocl = e / 576, rr = e - ocl * 576;
        wk[ocl * 577 + rr] = w[(oc0base + ocl) * 576 + rr];
    }
    __syncthreads();

    const int im = tid >> 5;
    const int r  = tid & 31;
    const int ocg = r & 7, oh = r >> 3;
    const int oc0 = ocg * 4;

    float acc[4][4];
    #pragma unroll
    for (int i = 0; i < 4; i++)
        #pragma unroll
        for (int j = 0; j < 4; j++) acc[i][j] = 0.0f;

    const float* ibase = img + im * 2304 + oh * 6;
    for (int ic = 0; ic < 64; ic++) {
        const float* ib = ibase + ic * 36;
        const float* wb = wk + ic * 9;
        #pragma unroll
        for (int kh = 0; kh < 3; kh++) {
            #pragma unroll
            for (int kw = 0; kw < 3; kw++) {
                const float x0 = ib[kh * 6 + kw];
                const float x1 = ib[kh * 6 + kw + 1];
                const float x2 = ib[kh * 6 + kw + 2];
                const float x3 = ib[kh * 6 + kw + 3];
                #pragma unroll
                for (int i = 0; i < 4; i++) {
                    const float wv = wb[(oc0 + i) * 577 + kh * 3 + kw];
                    acc[i][0] += wv * x0;
                    acc[i][1] += wv * x1;
                    acc[i][2] += wv * x2;
                    acc[i][3] += wv * x3;
                }
            }
        }
    }
    const int n = nbase + im;
    #pragma unroll
    for (int i = 0; i < 4; i++) {
        const int oc = oc0base + oc0 + i;
        const float bi = bias[oc];
        #pragma unroll
        for (int j = 0; j < 4; j++) {
            float v = acc[i][j] + bi;
            out[(size_t)n * 1024 + oc * 16 + oh * 4 + j] = v > 0.0f ? v : 0.0f;
        }
    }
}

// ---------------------------------------------------------------------------
// GEMM (NT) f32x2: C[M,N] = act(A[M,K]*B[N,K]^T + b1 (+ b2))
// 128x64 block tile, 128 threads, 8x8 micro-tile (m-paired acc, b splats),
// K chunk 16, k-major smem, register-buffered global prefetch.
// Requires M%128==0, N%64==0, K%16==0.
// ---------------------------------------------------------------------------
template <bool RELU>
__global__ __launch_bounds__(128)
void gemm_nt_f2(const float* __restrict__ A, const float* __restrict__ B,
                const float* __restrict__ b1, const float* __restrict__ b2,
                float* __restrict__ C, int K, int N)
{
    __shared__ __align__(16) float As[16 * 132];
    __shared__ __align__(16) float Bs[16 * 68];

    const int tid = threadIdx.x;
    const int m0 = blockIdx.y * 128;
    const int n0 = blockIdx.x * 64;
    const int ty = tid >> 3;      // 0..15 -> 8 m rows each
    const int tx = tid & 7;       // 0..7  -> 8 n cols each

    ull acc[4][8];
    #pragma unroll
    for (int i = 0; i < 4; i++)
        #pragma unroll
        for (int j = 0; j < 8; j++) acc[i][j] = 0ull;

    float4 pa[4], pb[2];

    // prefetch chunk 0
    #pragma unroll
    for (int l = 0; l < 4; l++) {
        const int id = tid + l * 128, row = id >> 2, c4 = (id & 3) * 4;
        pa[l] = *(const float4*)(A + (size_t)(m0 + row) * K + c4);
    }
    #pragma unroll
    for (int l = 0; l < 2; l++) {
        const int id = tid + l * 128, row = id >> 2, c4 = (id & 3) * 4;
        pb[l] = *(const float4*)(B + (size_t)(n0 + row) * K + c4);
    }

    for (int k0 = 0; k0 < K; k0 += 16) {
        // store chunk to smem (k-major transpose)
        #pragma unroll
        for (int l = 0; l < 4; l++) {
            const int id = tid + l * 128, row = id >> 2, c4 = (id & 3) * 4;
            As[(c4 + 0) * 132 + row] = pa[l].x;
            As[(c4 + 1) * 132 + row] = pa[l].y;
            As[(c4 + 2) * 132 + row] = pa[l].z;
            As[(c4 + 3) * 132 + row] = pa[l].w;
        }
        #pragma unroll
        for (int l = 0; l < 2; l++) {
            const int id = tid + l * 128, row = id >> 2, c4 = (id & 3) * 4;
            Bs[(c4 + 0) * 68 + row] = pb[l].x;
            Bs[(c4 + 1) * 68 + row] = pb[l].y;
            Bs[(c4 + 2) * 68 + row] = pb[l].z;
            Bs[(c4 + 3) * 68 + row] = pb[l].w;
        }
        __syncthreads();

        if (k0 + 16 < K) {
            #pragma unroll
            for (int l = 0; l < 4; l++) {
                const int id = tid + l * 128, row = id >> 2, c4 = (id & 3) * 4;
                pa[l] = *(const float4*)(A + (size_t)(m0 + row) * K + k0 + 16 + c4);
            }
            #pragma unroll
            for (int l = 0; l < 2; l++) {
                const int id = tid + l * 128, row = id >> 2, c4 = (id & 3) * 4;
                pb[l] = *(const float4*)(B + (size_t)(n0 + row) * K + k0 + 16 + c4);
            }
        }

        #pragma unroll
        for (int kk = 0; kk < 16; kk++) {
            const ulonglong2 av0 = *(const ulonglong2*)(As + kk * 132 + ty * 8);
            const ulonglong2 av1 = *(const ulonglong2*)(As + kk * 132 + ty * 8 + 4);
            const ull ap[4] = {av0.x, av0.y, av1.x, av1.y};
            const float4 b0 = *(const float4*)(Bs + kk * 68 + tx * 8);
            const float4 b1v = *(const float4*)(Bs + kk * 68 + tx * 8 + 4);
            const ull s[8] = {pack2(b0.x, b0.x),  pack2(b0.y, b0.y),
                              pack2(b0.z, b0.z),  pack2(b0.w, b0.w),
                              pack2(b1v.x, b1v.x), pack2(b1v.y, b1v.y),
                              pack2(b1v.z, b1v.z), pack2(b1v.w, b1v.w)};
            #pragma unroll
            for (int i = 0; i < 4; i++)
                #pragma unroll
                for (int j = 0; j < 8; j++)
                    ffma2(acc[i][j], ap[i], s[j]);
        }
        __syncthreads();
    }

    #pragma unroll
    for (int j = 0; j < 8; j++) {
        const int col = n0 + tx * 8 + j;
        const float bb = b1[col] + (b2 ? b2[col] : 0.0f);
        #pragma unroll
        for (int i = 0; i < 4; i++) {
            const float2 v = unpack2(acc[i][j]);
            float r0 = v.x + bb, r1 = v.y + bb;
            if (RELU) { r0 = r0 > 0.0f ? r0 : 0.0f; r1 = r1 > 0.0f ? r1 : 0.0f; }
            C[(size_t)(m0 + ty * 8 + 2 * i) * N + col] = r0;
            C[(size_t)(m0 + ty * 8 + 2 * i + 1) * N + col] = r1;
        }
    }
}

// ---------------------------------------------------------------------------
// LSTM: 64 blocks x 256 threads. Block b owns hidden cols [4b, 4b+4).
// f32x2 k-packed gate dot products.
// ---------------------------------------------------------------------------
__global__ __launch_bounds__(256, 1)
void lstm_kernel(const float* __restrict__ gx, const float* __restrict__ whh,
                 const int* __restrict__ done,
                 const float* __restrict__ h0, const float* __restrict__ c0,
                 float* __restrict__ out)
{
    extern __shared__ __align__(16) float sm[];
    float* ws     = sm;                    // 16 rows, stride 264
    float* h_s    = sm + 16 * 264;         // 32 rows, stride 264
    float* gate_s = h_s + 32 * 264;        // 512
    float* c_s    = gate_s + 512;          // 128

    const int tid = threadIdx.x;
    const int j0 = blockIdx.x * 4;

    #pragma unroll
    for (int l = 0; l < 4; l++) {
        const int id = tid + l * 256;
        const int r = id >> 6;
        const int c4 = (id & 63) * 4;
        const int g = r >> 2, jj = r & 3;
        *(float4*)(ws + r * 264 + c4) =
            *(const float4*)(whh + (size_t)(g * 256 + j0 + jj) * 256 + c4);
    }
    if (tid < 128) {
        const int b = tid >> 2, jj = tid & 3;
        c_s[tid] = c0[b * 256 + j0 + jj];
    }
    unsigned bar_gen = 0;
    if (tid == 0) bar_gen = *((volatile unsigned*)&g_gen);
    __syncthreads();

    const int u = tid & 7;
    const int b = tid >> 3;
    const int jj = u & 3, gh = u >> 2;
    const float* w0 = ws + ((2 * gh) * 4 + jj) * 264;
    const float* w1 = ws + ((2 * gh + 1) * 4 + jj) * 264;
    const float* hb = h_s + b * 264;

    for (int t = 0; t < 64; t++) {
        const float* hsrc = (t == 0) ? h0 : g_hbuf[(t - 1) & 1];
        const int* dn = done + t * 32;
        #pragma unroll
        for (int l = 0; l < 8; l++) {
            const int f = tid + l * 256;
            const int bb = f >> 6;
            const int kc = (f & 63) * 4;
            const float m = 1.0f - (float)dn[bb];
            float4 v = *(const float4*)(hsrc + bb * 256 + kc);
            v.x *= m; v.y *= m; v.z *= m; v.w *= m;
            *(float4*)(h_s + bb * 264 + kc) = v;
        }
        __syncthreads();

        ull a0 = 0ull, a1 = 0ull, d0 = 0ull, d1 = 0ull;
        #pragma unroll 8
        for (int k = 0; k < 256; k += 4) {
            const ulonglong2 h2 = *(const ulonglong2*)(hb + k);
            const ulonglong2 wa = *(const ulonglong2*)(w0 + k);
            const ulonglong2 wb2 = *(const ulonglong2*)(w1 + k);
            ffma2(a0, h2.x, wa.x);  ffma2(a1, h2.y, wa.y);
            ffma2(d0, h2.x, wb2.x); ffma2(d1, h2.y, wb2.y);
        }
        const float2 fa0 = unpack2(a0), fa1 = unpack2(a1);
        const float2 fd0 = unpack2(d0), fd1 = unpack2(d1);
        const int row = t * 32 + b;
        const float g0v = ((fa0.x + fa0.y) + (fa1.x + fa1.y)) +
                          gx[(size_t)row * 1024 + (2 * gh) * 256 + j0 + jj];
        const float g1v = ((fd0.x + fd0.y) + (fd1.x + fd1.y)) +
                          gx[(size_t)row * 1024 + (2 * gh + 1) * 256 + j0 + jj];
        gate_s[(b * 4 + jj) * 4 + 2 * gh] = g0v;
        gate_s[(b * 4 + jj) * 4 + 2 * gh + 1] = g1v;
        __syncthreads();

        if (tid < 128) {
            const int bb = tid >> 2, j2 = tid & 3;
            const float* gp = gate_s + tid * 4;
            const float gi = gp[0], gf = gp[1], gg = gp[2], go = gp[3];
            const float m = 1.0f - (float)dn[bb];
            const float cold = c_s[tid] * m;
            const float si = 1.0f / (1.0f + __expf(-gi));
            const float sf = 1.0f / (1.0f + __expf(-gf));
            const float so = 1.0f / (1.0f + __expf(-go));
            const float cn = sf * cold + si * tanhf(gg);
            const float h = so * tanhf(cn);
            c_s[tid] = cn;
            const int j = j0 + j2;
            g_hbuf[t & 1][bb * 256 + j] = h;
            out[(size_t)(t * 32 + bb) * 256 + j] = h;
        }
        __threadfence();
        __syncthreads();

        if (t < 63) {
            if (tid == 0) {
                const unsigned prev = atomicAdd(&g_count, 1);
                if (prev == gridDim.x - 1) {
                    g_count = 0;
                    __threadfence();
                    atomicAdd(&g_gen, 1);
                } else {
                    while (*((volatile unsigned*)&g_gen) == bar_gen) { }
                }
                bar_gen++;
                __threadfence();
            }
            __syncthreads();
        }
    }
}

// ---------------------------------------------------------------------------
extern "C" void kernel_launch(void* const* d_in, const int* in_sizes, int n_in,
                              void* d_out, int out_size)
{
    const float* x    = (const float*)d_in[0];
    const int*   done = (const int*)d_in[1];
    const float* w1   = (const float*)d_in[2];
    const float* b1   = (const float*)d_in[3];
    const float* w2   = (const float*)d_in[4];
    const float* b2   = (const float*)d_in[5];
    const float* w3   = (const float*)d_in[6];
    const float* b3   = (const float*)d_in[7];
    const float* fcw  = (const float*)d_in[8];
    const float* fcb  = (const float*)d_in[9];
    const float* wih  = (const float*)d_in[10];
    const float* whh  = (const float*)d_in[11];
    const float* bih  = (const float*)d_in[12];
    const float* bhh  = (const float*)d_in[13];
    const float* h0   = (const float*)d_in[14];
    const float* c0   = (const float*)d_in[15];
    float* out = (float*)d_out;

    float *buf1, *buf2, *buf3, *feats, *gatesx;
    cudaGetSymbolAddress((void**)&buf1,   g_buf1);
    cudaGetSymbolAddress((void**)&buf2,   g_buf2);
    cudaGetSymbolAddress((void**)&buf3,   g_buf3);
    cudaGetSymbolAddress((void**)&feats,  g_feats);
    cudaGetSymbolAddress((void**)&gatesx, g_gatesx);

    cudaFuncSetAttribute(conv1_kernel, cudaFuncAttributeMaxDynamicSharedMemorySize, SMEM1);
    cudaFuncSetAttribute(conv2_kernel, cudaFuncAttributeMaxDynamicSharedMemorySize, SMEM2);
    cudaFuncSetAttribute(conv3_kernel, cudaFuncAttributeMaxDynamicSharedMemorySize, SMEM3);
    cudaFuncSetAttribute(lstm_kernel,  cudaFuncAttributeMaxDynamicSharedMemorySize, SMEML);

    conv1_kernel<<<2048, 192, SMEM1>>>(x, w1, b1, buf1);
    conv2_kernel<<<1024, 192, SMEM2>>>(buf1, w2, b2, buf2);
    conv3_kernel<<<1024, 128, SMEM3>>>(buf2, w3, b3, buf3);
    gemm_nt_f2<true><<<dim3(8, 16), 128>>>(buf3, fcw, fcb, nullptr, feats, 1024, 512);
    gemm_nt_f2<false><<<dim3(16, 16), 128>>>(feats, wih, bih, bhh, gatesx, 512, 1024);
    lstm_kernel<<<64, 256, SMEML>>>(gatesx, whh, done, h0, c0, out);
}

// round 6
// speedup vs baseline: 1.2667x; 1.2667x over previous
#include <cuda_runtime.h>
#include <cuda_bf16.h>
#include <math.h>
#include <cstdint>

typedef unsigned long long ull;
typedef uint32_t u32;

// ===========================================================================
// Static scratch
// ===========================================================================
__device__ float g_buf1[2048 * 32 * 15 * 15];
__device__ float g_buf2[2048 * 64 * 6 * 6];
__device__ float g_buf3[2048 * 1024];
__device__ float g_feats[2048 * 512];
__device__ float g_gatesx[2048 * 1024];
__device__ float g_hbuf[2][32 * 256];
__device__ unsigned g_count;
__device__ unsigned g_gen;

#define SMEM2 ((7200 + 64 * 129) * 4)
#define SMEM3 ((9216 + 32 * 577) * 4)
#define SMEML ((16 * 264 + 32 * 264 + 512 + 128) * 4)

// ===========================================================================
// conv1 via mma.sync (bf16x3): stride-4 8x8 conv == 2x2 stride-1 conv over
// 64 phase channels. One CTA per image.
//   X'[gh*16+gw][k=c*16+s*4+p] = x[n][c][4gh+s][4gw+p]/255   (256 rows, 64 ch)
//   y[oc][oh][ow] = sum_q sum_k Wq[oc][k] * X'[(oh+dh)*16+(ow+dw)][k]
// A rows padded to 144B -> all fragment LDS conflict-free.
// ===========================================================================
#define A_STRIDE 144
#define A_BYTES  (273 * A_STRIDE)          // 39312
#define BQ_BYTES (32 * A_STRIDE)           // 4608
#define OFF_AHI  128
#define OFF_ALO  (OFF_AHI + A_BYTES)
#define OFF_BHI  (OFF_ALO + A_BYTES)
#define OFF_BLO  (OFF_BHI + 4 * BQ_BYTES)
#define C1_SMEM  (OFF_BLO + 4 * BQ_BYTES)  // 115616 bytes

__device__ __forceinline__ void mma16816(float* d, const u32* a, const u32* b) {
    asm volatile(
        "mma.sync.aligned.m16n8k16.row.col.f32.bf16.bf16.f32 "
        "{%0,%1,%2,%3}, {%4,%5,%6,%7}, {%8,%9}, {%0,%1,%2,%3};"
        : "+f"(d[0]), "+f"(d[1]), "+f"(d[2]), "+f"(d[3])
        : "r"(a[0]), "r"(a[1]), "r"(a[2]), "r"(a[3]), "r"(b[0]), "r"(b[1]));
}

__device__ __forceinline__ ull pack_hi4(float4 v, float4* rem) {
    __nv_bfloat16 h0 = __float2bfloat16_rn(v.x);
    __nv_bfloat16 h1 = __float2bfloat16_rn(v.y);
    __nv_bfloat16 h2 = __float2bfloat16_rn(v.z);
    __nv_bfloat16 h3 = __float2bfloat16_rn(v.w);
    rem->x = v.x - __bfloat162float(h0);
    rem->y = v.y - __bfloat162float(h1);
    rem->z = v.z - __bfloat162float(h2);
    rem->w = v.w - __bfloat162float(h3);
    return (ull)__bfloat16_as_ushort(h0) |
           ((ull)__bfloat16_as_ushort(h1) << 16) |
           ((ull)__bfloat16_as_ushort(h2) << 32) |
           ((ull)__bfloat16_as_ushort(h3) << 48);
}
__device__ __forceinline__ ull pack_lo4(float4 v) {
    return (ull)__bfloat16_as_ushort(__float2bfloat16_rn(v.x)) |
           ((ull)__bfloat16_as_ushort(__float2bfloat16_rn(v.y)) << 16) |
           ((ull)__bfloat16_as_ushort(__float2bfloat16_rn(v.z)) << 32) |
           ((ull)__bfloat16_as_ushort(__float2bfloat16_rn(v.w)) << 48);
}

__global__ __launch_bounds__(256, 1)
void conv1_mma_kernel(const float* __restrict__ x, const float* __restrict__ w,
                      const float* __restrict__ bias, float* __restrict__ out)
{
    extern __shared__ __align__(16) char smem[];
    float* sbias = (float*)smem;
    char* Ahi = smem + OFF_AHI;
    char* Alo = smem + OFF_ALO;
    char* Bhi = smem + OFF_BHI;
    char* Blo = smem + OFF_BLO;

    const int tid = threadIdx.x;
    const int n = blockIdx.x;
    const float inv255 = 1.0f / 255.0f;

    if (tid < 32) sbias[tid] = bias[tid];

    // ---- fill A (phase tensor X', hi/lo) : 256 rows x 16 ch-quads ----
    for (int idx = tid; idx < 4096; idx += 256) {
        const int row = idx >> 4;         // gh*16+gw
        const int cs  = idx & 15;         // c*4+s
        const int c = cs >> 2, s = cs & 3;
        const int gh = row >> 4, gw = row & 15;
        float4 v = *(const float4*)(x + (size_t)((n * 4 + c) * 64 + 4 * gh + s) * 64 + 4 * gw);
        v.x *= inv255; v.y *= inv255; v.z *= inv255; v.w *= inv255;
        float4 rem;
        const ull ph = pack_hi4(v, &rem);
        const ull pl = pack_lo4(rem);
        const int off = row * A_STRIDE + cs * 8;
        *(ull*)(Ahi + off) = ph;
        *(ull*)(Alo + off) = pl;
    }
    // zero pad rows 256..272
    for (int i = tid; i < 612; i += 256) {
        const int half = i / 306;
        const int off = 256 * A_STRIDE + (i - half * 306) * 8;
        *(ull*)((half ? Alo : Ahi) + off) = 0ull;
    }
    // ---- fill B (4 quadrant weight tiles, hi/lo) ----
    for (int idx = tid; idx < 2048; idx += 256) {
        const int q  = idx >> 9;
        const int oc = (idx >> 4) & 31;
        const int cs = idx & 15;
        const int c = cs >> 2, s = cs & 3;
        const int dh = q >> 1, dw = q & 1;
        float4 v = *(const float4*)(w + (size_t)((oc * 4 + c) * 8 + 4 * dh + s) * 8 + 4 * dw);
        float4 rem;
        const ull ph = pack_hi4(v, &rem);
        const ull pl = pack_lo4(rem);
        const int off = q * BQ_BYTES + oc * A_STRIDE + cs * 8;
        *(ull*)(Bhi + off) = ph;
        *(ull*)(Blo + off) = pl;
    }
    __syncthreads();

    // ---- compute: 8 warps, each 2 m-tiles x 4 n-tiles ----
    const int wid = tid >> 5, lane = tid & 31;
    const int g = lane >> 2, t = lane & 3;

    float acc[2][4][4];
    #pragma unroll
    for (int m = 0; m < 2; m++)
        #pragma unroll
        for (int nt = 0; nt < 4; nt++)
            #pragma unroll
            for (int r = 0; r < 4; r++) acc[m][nt][r] = 0.0f;

    const int mt0 = wid, mt1 = wid + 8;

    #pragma unroll
    for (int q = 0; q < 4; q++) {
        const int r0 = (q >> 1) * 16 + (q & 1);
        const char* Bq_hi = Bhi + q * BQ_BYTES;
        const char* Bq_lo = Blo + q * BQ_BYTES;
        const int arow0 = (mt0 * 16 + r0 + g) * A_STRIDE;
        const int arow1 = (mt1 * 16 + r0 + g) * A_STRIDE;

        #pragma unroll
        for (int ks = 0; ks < 4; ks++) {
            const int co = ks * 32 + t * 4;
            u32 ahi[2][4], alo[2][4], bhi[4][2], blo[4][2];
            #pragma unroll
            for (int m = 0; m < 2; m++) {
                const int rb = (m ? arow1 : arow0) + co;
                ahi[m][0] = *(const u32*)(Ahi + rb);
                ahi[m][1] = *(const u32*)(Ahi + rb + 8 * A_STRIDE);
                ahi[m][2] = *(const u32*)(Ahi + rb + 16);
                ahi[m][3] = *(const u32*)(Ahi + rb + 8 * A_STRIDE + 16);
                alo[m][0] = *(const u32*)(Alo + rb);
                alo[m][1] = *(const u32*)(Alo + rb + 8 * A_STRIDE);
                alo[m][2] = *(const u32*)(Alo + rb + 16);
                alo[m][3] = *(const u32*)(Alo + rb + 8 * A_STRIDE + 16);
            }
            #pragma unroll
            for (int nt = 0; nt < 4; nt++) {
                const int bo = (nt * 8 + g) * A_STRIDE + co;
                bhi[nt][0] = *(const u32*)(Bq_hi + bo);
                bhi[nt][1] = *(const u32*)(Bq_hi + bo + 16);
                blo[nt][0] = *(const u32*)(Bq_lo + bo);
                blo[nt][1] = *(const u32*)(Bq_lo + bo + 16);
            }
            #pragma unroll
            for (int m = 0; m < 2; m++)
                #pragma unroll
                for (int nt = 0; nt < 4; nt++) {
                    mma16816(acc[m][nt], ahi[m], bhi[nt]);
                    mma16816(acc[m][nt], alo[m], bhi[nt]);
                    mma16816(acc[m][nt], ahi[m], blo[nt]);
                }
        }
    }

    // ---- epilogue: D[pos][oc] -> out[n][oc][oh][ow], bias + relu ----
    float* ob = out + (size_t)n * 7200;
    #pragma unroll
    for (int m = 0; m < 2; m++) {
        const int mt = m ? mt1 : mt0;
        const int r1 = mt * 16 + g;
        const int r2 = r1 + 8;
        const int oh1 = r1 >> 4, ow1 = r1 & 15;
        const int oh2 = r2 >> 4, ow2 = r2 & 15;
        #pragma unroll
        for (int nt = 0; nt < 4; nt++) {
            const int c0 = nt * 8 + 2 * t;
            const float b0 = sbias[c0], b1 = sbias[c0 + 1];
            if (oh1 < 15 && ow1 < 15) {
                float v0 = acc[m][nt][0] + b0;
                float v1 = acc[m][nt][1] + b1;
                ob[c0 * 225 + oh1 * 15 + ow1] = v0 > 0.0f ? v0 : 0.0f;
                ob[(c0 + 1) * 225 + oh1 * 15 + ow1] = v1 > 0.0f ? v1 : 0.0f;
            }
            if (oh2 < 15 && ow2 < 15) {
                float v2 = acc[m][nt][2] + b0;
                float v3 = acc[m][nt][3] + b1;
                ob[c0 * 225 + oh2 * 15 + ow2] = v2 > 0.0f ? v2 : 0.0f;
                ob[(c0 + 1) * 225 + oh2 * 15 + ow2] = v3 > 0.0f ? v3 : 0.0f;
            }
        }
    }
}

// ===========================================================================
// conv2 (R2 scalar): in (n,32,15,15) -> relu -> out (n,64,6,6), k=4 s=2
// ===========================================================================
__global__ __launch_bounds__(192, 3)
void conv2_kernel(const float* __restrict__ in, const float* __restrict__ w,
                  const float* __restrict__ bias, float* __restrict__ out)
{
    extern __shared__ float sm[];
    float* img = sm;
    float* wk  = sm + 7200;

    const int tid = threadIdx.x;
    const int n = blockIdx.x;

    const float4* ip = (const float4*)(in + (size_t)n * 7200);
    for (int i = tid; i < 1800; i += 192) ((float4*)img)[i] = ip[i];

    const int ocg = tid & 15;
    const int owg = (tid >> 4) & 1;
    const int oh  = tid >> 5;
    const int oc0 = ocg * 4, ow0 = owg * 3;

    float acc[4][3];
    #pragma unroll
    for (int i = 0; i < 4; i++)
        #pragma unroll
        for (int j = 0; j < 3; j++) acc[i][j] = 0.0f;

    for (int icc = 0; icc < 4; icc++) {
        __syncthreads();
        for (int e = tid; e < 8192; e += 192) {
            int oc = e >> 7, rr = e & 127;
            wk[oc * 129 + rr] = w[oc * 512 + icc * 128 + rr];
        }
        __syncthreads();

        for (int ici = 0; ici < 8; ici++) {
            const float* ib = img + (icc * 8 + ici) * 225 + (oh * 2) * 15 + ow0 * 2;
            const float* wb = wk + ici * 16;
            #pragma unroll
            for (int kh = 0; kh < 4; kh++) {
                #pragma unroll
                for (int kw = 0; kw < 4; kw++) {
                    const float x0 = ib[kh * 15 + kw];
                    const float x1 = ib[kh * 15 + kw + 2];
                    const float x2 = ib[kh * 15 + kw + 4];
                    #pragma unroll
                    for (int i = 0; i < 4; i++) {
                        const float wv = wb[(oc0 + i) * 129 + kh * 4 + kw];
                        acc[i][0] += wv * x0;
                        acc[i][1] += wv * x1;
                        acc[i][2] += wv * x2;
                    }
                }
            }
        }
    }
    float* ob = out + (((size_t)n * 64 + oc0) * 6 + oh) * 6 + ow0;
    #pragma unroll
    for (int i = 0; i < 4; i++) {
        const float bi = bias[oc0 + i];
        #pragma unroll
        for (int j = 0; j < 3; j++) {
            float v = acc[i][j] + bi;
            ob[i * 36 + j] = v > 0.0f ? v : 0.0f;
        }
    }
}

// ===========================================================================
// conv3 (R2 scalar): in (n,64,6,6) -> relu -> flatten (n, 1024), k=3 s=1
// ===========================================================================
__global__ __launch_bounds__(128, 2)
void conv3_kernel(const float* __restrict__ in, const float* __restrict__ w,
                  const float* __restrict__ bias, float* __restrict__ out)
{
    extern __shared__ float sm[];
    float* img = sm;
    float* wk  = sm + 9216;

    const int tid = threadIdx.x;
    const int nbase = (blockIdx.x >> 1) * 4;
    const int oc0base = (blockIdx.x & 1) * 32;

    const float4* ip = (const float4*)(in + (size_t)nbase * 2304);
    for (int i = tid; i < 2304; i += 128) ((float4*)img)[i] = ip[i];
    for (int e = tid; e < 18432; e += 128) {
        int ocl = e / 576, rr = e - ocl * 576;
        wk[ocl * 577 + rr] = w[(oc0base + ocl) * 576 + rr];
    }
    __syncthreads();

    const int im = tid >> 5;
    const int r  = tid & 31;
    const int ocg = r & 7, oh = r >> 3;
    const int oc0 = ocg * 4;

    float acc[4][4];
    #pragma unroll
    for (int i = 0; i < 4; i++)
        #pragma unroll
        for (int j = 0; j < 4; j++) acc[i][j] = 0.0f;

    const float* ibase = img + im * 2304 + oh * 6;
    for (int ic = 0; ic < 64; ic++) {
        const float* ib = ibase + ic * 36;
        const float* wb = wk + ic * 9;
        #pragma unroll
        for (int kh = 0; kh < 3; kh++) {
            #pragma unroll
            for (int kw = 0; kw < 3; kw++) {
                const float x0 = ib[kh * 6 + kw];
                const float x1 = ib[kh * 6 + kw + 1];
                const float x2 = ib[kh * 6 + kw + 2];
                const float x3 = ib[kh * 6 + kw + 3];
                #pragma unroll
                for (int i = 0; i < 4; i++) {
                    const float wv = wb[(oc0 + i) * 577 + kh * 3 + kw];
                    acc[i][0] += wv * x0;
                    acc[i][1] += wv * x1;
                    acc[i][2] += wv * x2;
                    acc[i][3] += wv * x3;
                }
            }
        }
    }
    const int n = nbase + im;
    #pragma unroll
    for (int i = 0; i < 4; i++) {
        const int oc = oc0base + oc0 + i;
        const float bi = bias[oc];
        #pragma unroll
        for (int j = 0; j < 4; j++) {
            float v = acc[i][j] + bi;
            out[(size_t)n * 1024 + oc * 16 + oh * 4 + j] = v > 0.0f ? v : 0.0f;
        }
    }
}

// ===========================================================================
// GEMM (NT, R2 scalar): C[M,N] = act(A[M,K]*B[N,K]^T + b1 (+b2))
// ===========================================================================
template <bool RELU>
__global__ __launch_bounds__(256)
void gemm_nt_kernel(const float* __restrict__ A, const float* __restrict__ B,
                    const float* __restrict__ b1, const float* __restrict__ b2,
                    float* __restrict__ C, int K, int N)
{
    __shared__ float As[32 * 68];
    __shared__ float Bs[32 * 68];

    const int tid = threadIdx.x;
    const int m0 = blockIdx.y * 64;
    const int n0 = blockIdx.x * 64;
    const int ty = tid >> 4, tx = tid & 15;

    float acc[4][4];
    #pragma unroll
    for (int i = 0; i < 4; i++)
        #pragma unroll
        for (int j = 0; j < 4; j++) acc[i][j] = 0.0f;

    for (int k0 = 0; k0 < K; k0 += 32) {
        #pragma unroll
        for (int l = 0; l < 2; l++) {
            const int id = tid + l * 256;
            const int row = id >> 3;
            const int c4 = (id & 7) * 4;
            float4 av = *(const float4*)(A + (size_t)(m0 + row) * K + k0 + c4);
            float4 bv = *(const float4*)(B + (size_t)(n0 + row) * K + k0 + c4);
            As[(c4 + 0) * 68 + row] = av.x;
            As[(c4 + 1) * 68 + row] = av.y;
            As[(c4 + 2) * 68 + row] = av.z;
            As[(c4 + 3) * 68 + row] = av.w;
            Bs[(c4 + 0) * 68 + row] = bv.x;
            Bs[(c4 + 1) * 68 + row] = bv.y;
            Bs[(c4 + 2) * 68 + row] = bv.z;
            Bs[(c4 + 3) * 68 + row] = bv.w;
        }
        __syncthreads();
        #pragma unroll
        for (int kk = 0; kk < 32; kk++) {
            const float4 av = *(const float4*)(As + kk * 68 + ty * 4);
            const float4 bv = *(const float4*)(Bs + kk * 68 + tx * 4);
            acc[0][0] += av.x * bv.x; acc[0][1] += av.x * bv.y;
            acc[0][2] += av.x * bv.z; acc[0][3] += av.x * bv.w;
            acc[1][0] += av.y * bv.x; acc[1][1] += av.y * bv.y;
            acc[1][2] += av.y * bv.z; acc[1][3] += av.y * bv.w;
            acc[2][0] += av.z * bv.x; acc[2][1] += av.z * bv.y;
            acc[2][2] += av.z * bv.z; acc[2][3] += av.z * bv.w;
            acc[3][0] += av.w * bv.x; acc[3][1] += av.w * bv.y;
            acc[3][2] += av.w * bv.z; acc[3][3] += av.w * bv.w;
        }
        __syncthreads();
    }

    #pragma unroll
    for (int j = 0; j < 4; j++) {
        const int col = n0 + tx * 4 + j;
        float bb = b1[col] + (b2 ? b2[col] : 0.0f);
        #pragma unroll
        for (int i = 0; i < 4; i++) {
            float v = acc[i][j] + bb;
            if (RELU) v = v > 0.0f ? v : 0.0f;
            C[(size_t)(m0 + ty * 4 + i) * N + col] = v;
        }
    }
}

// ===========================================================================
// LSTM (R2): 64 blocks x 256 threads
// ===========================================================================
__global__ __launch_bounds__(256, 1)
void lstm_kernel(const float* __restrict__ gx, const float* __restrict__ whh,
                 const int* __restrict__ done,
                 const float* __restrict__ h0, const float* __restrict__ c0,
                 float* __restrict__ out)
{
    extern __shared__ float sm[];
    float* ws     = sm;
    float* h_s    = sm + 16 * 264;
    float* gate_s = h_s + 32 * 264;
    float* c_s    = gate_s + 512;

    const int tid = threadIdx.x;
    const int j0 = blockIdx.x * 4;

    #pragma unroll
    for (int l = 0; l < 4; l++) {
        const int id = tid + l * 256;
        const int r = id >> 6;
        const int c4 = (id & 63) * 4;
        const int g = r >> 2, jj = r & 3;
        *(float4*)(ws + r * 264 + c4) =
            *(const float4*)(whh + (size_t)(g * 256 + j0 + jj) * 256 + c4);
    }
    if (tid < 128) {
        const int b = tid >> 2, jj = tid & 3;
        c_s[tid] = c0[b * 256 + j0 + jj];
    }
    unsigned bar_gen = 0;
    if (tid == 0) bar_gen = *((volatile unsigned*)&g_gen);
    __syncthreads();

    const int u = tid & 7;
    const int b = tid >> 3;
    const int jj = u & 3, gh = u >> 2;
    const float* w0 = ws + ((2 * gh) * 4 + jj) * 264;
    const float* w1 = ws + ((2 * gh + 1) * 4 + jj) * 264;
    const float* hb = h_s + b * 264;

    for (int t = 0; t < 64; t++) {
        const float* hsrc = (t == 0) ? h0 : g_hbuf[(t - 1) & 1];
        const int* dn = done + t * 32;
        #pragma unroll
        for (int l = 0; l < 8; l++) {
            const int f = tid + l * 256;
            const int bb = f >> 6;
            const int kc = (f & 63) * 4;
            const float m = 1.0f - (float)dn[bb];
            float4 v = *(const float4*)(hsrc + bb * 256 + kc);
            v.x *= m; v.y *= m; v.z *= m; v.w *= m;
            *(float4*)(h_s + bb * 264 + kc) = v;
        }
        __syncthreads();

        float s00 = 0, s01 = 0, s02 = 0, s03 = 0;
        float s10 = 0, s11 = 0, s12 = 0, s13 = 0;
        #pragma unroll 8
        for (int k = 0; k < 256; k += 4) {
            const float4 h4 = *(const float4*)(hb + k);
            const float4 wa = *(const float4*)(w0 + k);
            const float4 wb4 = *(const float4*)(w1 + k);
            s00 += h4.x * wa.x;  s01 += h4.y * wa.y;
            s02 += h4.z * wa.z;  s03 += h4.w * wa.w;
            s10 += h4.x * wb4.x; s11 += h4.y * wb4.y;
            s12 += h4.z * wb4.z; s13 += h4.w * wb4.w;
        }
        const int row = t * 32 + b;
        const float g0v = ((s00 + s01) + (s02 + s03)) +
                          gx[(size_t)row * 1024 + (2 * gh) * 256 + j0 + jj];
        const float g1v = ((s10 + s11) + (s12 + s13)) +
                          gx[(size_t)row * 1024 + (2 * gh + 1) * 256 + j0 + jj];
        gate_s[(b * 4 + jj) * 4 + 2 * gh] = g0v;
        gate_s[(b * 4 + jj) * 4 + 2 * gh + 1] = g1v;
        __syncthreads();

        if (tid < 128) {
            const int bb = tid >> 2, j2 = tid & 3;
            const float* gp = gate_s + tid * 4;
            const float gi = gp[0], gf = gp[1], gg = gp[2], go = gp[3];
            const float m = 1.0f - (float)dn[bb];
            const float cold = c_s[tid] * m;
            const float si = 1.0f / (1.0f + __expf(-gi));
            const float sf = 1.0f / (1.0f + __expf(-gf));
            const float so = 1.0f / (1.0f + __expf(-go));
            const float cn = sf * cold + si * tanhf(gg);
            const float h = so * tanhf(cn);
            c_s[tid] = cn;
            const int j = j0 + j2;
            g_hbuf[t & 1][bb * 256 + j] = h;
            out[(size_t)(t * 32 + bb) * 256 + j] = h;
        }
        __threadfence();
        __syncthreads();

        if (t < 63) {
            if (tid == 0) {
                const unsigned prev = atomicAdd(&g_count, 1);
                if (prev == gridDim.x - 1) {
                    g_count = 0;
                    __threadfence();
                    atomicAdd(&g_gen, 1);
                } else {
                    while (*((volatile unsigned*)&g_gen) == bar_gen) { }
                }
                bar_gen++;
                __threadfence();
            }
            __syncthreads();
        }
    }
}

// ===========================================================================
extern "C" void kernel_launch(void* const* d_in, const int* in_sizes, int n_in,
                              void* d_out, int out_size)
{
    const float* x    = (const float*)d_in[0];
    const int*   done = (const int*)d_in[1];
    const float* w1   = (const float*)d_in[2];
    const float* b1   = (const float*)d_in[3];
    const float* w2   = (const float*)d_in[4];
    const float* b2   = (const float*)d_in[5];
    const float* w3   = (const float*)d_in[6];
    const float* b3   = (const float*)d_in[7];
    const float* fcw  = (const float*)d_in[8];
    const float* fcb  = (const float*)d_in[9];
    const float* wih  = (const float*)d_in[10];
    const float* whh  = (const float*)d_in[11];
    const float* bih  = (const float*)d_in[12];
    const float* bhh  = (const float*)d_in[13];
    const float* h0   = (const float*)d_in[14];
    const float* c0   = (const float*)d_in[15];
    float* out = (float*)d_out;

    float *buf1, *buf2, *buf3, *feats, *gatesx;
    cudaGetSymbolAddress((void**)&buf1,   g_buf1);
    cudaGetSymbolAddress((void**)&buf2,   g_buf2);
    cudaGetSymbolAddress((void**)&buf3,   g_buf3);
    cudaGetSymbolAddress((void**)&feats,  g_feats);
    cudaGetSymbolAddress((void**)&gatesx, g_gatesx);

    cudaFuncSetAttribute(conv1_mma_kernel, cudaFuncAttributeMaxDynamicSharedMemorySize, C1_SMEM);
    cudaFuncSetAttribute(conv2_kernel, cudaFuncAttributeMaxDynamicSharedMemorySize, SMEM2);
    cudaFuncSetAttribute(conv3_kernel, cudaFuncAttributeMaxDynamicSharedMemorySize, SMEM3);
    cudaFuncSetAttribute(lstm_kernel,  cudaFuncAttributeMaxDynamicSharedMemorySize, SMEML);

    conv1_mma_kernel<<<2048, 256, C1_SMEM>>>(x, w1, b1, buf1);
    conv2_kernel<<<2048, 192, SMEM2>>>(buf1, w2, b2, buf2);
    conv3_kernel<<<1024, 128, SMEM3>>>(buf2, w3, b3, buf3);
    gemm_nt_kernel<true><<<dim3(8, 32), 256>>>(buf3, fcw, fcb, nullptr, feats, 1024, 512);
    gemm_nt_kernel<false><<<dim3(16, 32), 256>>>(feats, wih, bih, bhh, gatesx, 512, 1024);
    lstm_kernel<<<64, 256, SMEML>>>(gatesx, whh, done, h0, c0, out);
}

// round 7
// speedup vs baseline: 1.3774x; 1.0874x over previous
#include <cuda_runtime.h>
#include <cuda_bf16.h>
#include <math.h>
#include <cstdint>

typedef unsigned long long ull;
typedef uint32_t u32;

// ===========================================================================
// Static scratch
// ===========================================================================
__device__ float g_buf1[2048 * 32 * 15 * 15];
__device__ float g_buf2[2048 * 64 * 6 * 6];
__device__ float g_buf3[2048 * 1024];
__device__ float g_feats[2048 * 512];
__device__ float g_gatesx[2048 * 1024];
__device__ float g_hbuf[2][32 * 256];
__device__ unsigned g_count;
__device__ unsigned g_gen;

#define SMEM3 ((9216 + 32 * 577) * 4)
#define SMEML ((16 * 264 + 32 * 264 + 512 + 128) * 4)

// ===========================================================================
// bf16 helpers
// ===========================================================================
__device__ __forceinline__ void mma16816(float* d, const u32* a, const u32* b) {
    asm volatile(
        "mma.sync.aligned.m16n8k16.row.col.f32.bf16.bf16.f32 "
        "{%0,%1,%2,%3}, {%4,%5,%6,%7}, {%8,%9}, {%0,%1,%2,%3};"
        : "+f"(d[0]), "+f"(d[1]), "+f"(d[2]), "+f"(d[3])
        : "r"(a[0]), "r"(a[1]), "r"(a[2]), "r"(a[3]), "r"(b[0]), "r"(b[1]));
}

__device__ __forceinline__ ull pack_hi4(float4 v, float4* rem) {
    __nv_bfloat16 h0 = __float2bfloat16_rn(v.x);
    __nv_bfloat16 h1 = __float2bfloat16_rn(v.y);
    __nv_bfloat16 h2 = __float2bfloat16_rn(v.z);
    __nv_bfloat16 h3 = __float2bfloat16_rn(v.w);
    rem->x = v.x - __bfloat162float(h0);
    rem->y = v.y - __bfloat162float(h1);
    rem->z = v.z - __bfloat162float(h2);
    rem->w = v.w - __bfloat162float(h3);
    return (ull)__bfloat16_as_ushort(h0) |
           ((ull)__bfloat16_as_ushort(h1) << 16) |
           ((ull)__bfloat16_as_ushort(h2) << 32) |
           ((ull)__bfloat16_as_ushort(h3) << 48);
}
__device__ __forceinline__ ull pack_lo4(float4 v) {
    return (ull)__bfloat16_as_ushort(__float2bfloat16_rn(v.x)) |
           ((ull)__bfloat16_as_ushort(__float2bfloat16_rn(v.y)) << 16) |
           ((ull)__bfloat16_as_ushort(__float2bfloat16_rn(v.z)) << 32) |
           ((ull)__bfloat16_as_ushort(__float2bfloat16_rn(v.w)) << 48);
}

// ===========================================================================
// conv1 via mma.sync (bf16x3) — validated R6 version
// ===========================================================================
#define A_STRIDE 144
#define A_BYTES  (273 * A_STRIDE)
#define BQ_BYTES (32 * A_STRIDE)
#define OFF_AHI  128
#define OFF_ALO  (OFF_AHI + A_BYTES)
#define OFF_BHI  (OFF_ALO + A_BYTES)
#define OFF_BLO  (OFF_BHI + 4 * BQ_BYTES)
#define C1_SMEM  (OFF_BLO + 4 * BQ_BYTES)

__global__ __launch_bounds__(256, 1)
void conv1_mma_kernel(const float* __restrict__ x, const float* __restrict__ w,
                      const float* __restrict__ bias, float* __restrict__ out)
{
    extern __shared__ __align__(16) char smem[];
    float* sbias = (float*)smem;
    char* Ahi = smem + OFF_AHI;
    char* Alo = smem + OFF_ALO;
    char* Bhi = smem + OFF_BHI;
    char* Blo = smem + OFF_BLO;

    const int tid = threadIdx.x;
    const int n = blockIdx.x;
    const float inv255 = 1.0f / 255.0f;

    if (tid < 32) sbias[tid] = bias[tid];

    for (int idx = tid; idx < 4096; idx += 256) {
        const int row = idx >> 4;
        const int cs  = idx & 15;
        const int c = cs >> 2, s = cs & 3;
        const int gh = row >> 4, gw = row & 15;
        float4 v = *(const float4*)(x + (size_t)((n * 4 + c) * 64 + 4 * gh + s) * 64 + 4 * gw);
        v.x *= inv255; v.y *= inv255; v.z *= inv255; v.w *= inv255;
        float4 rem;
        const ull ph = pack_hi4(v, &rem);
        const ull pl = pack_lo4(rem);
        const int off = row * A_STRIDE + cs * 8;
        *(ull*)(Ahi + off) = ph;
        *(ull*)(Alo + off) = pl;
    }
    for (int i = tid; i < 612; i += 256) {
        const int half = i / 306;
        const int off = 256 * A_STRIDE + (i - half * 306) * 8;
        *(ull*)((half ? Alo : Ahi) + off) = 0ull;
    }
    for (int idx = tid; idx < 2048; idx += 256) {
        const int q  = idx >> 9;
        const int oc = (idx >> 4) & 31;
        const int cs = idx & 15;
        const int c = cs >> 2, s = cs & 3;
        const int dh = q >> 1, dw = q & 1;
        float4 v = *(const float4*)(w + (size_t)((oc * 4 + c) * 8 + 4 * dh + s) * 8 + 4 * dw);
        float4 rem;
        const ull ph = pack_hi4(v, &rem);
        const ull pl = pack_lo4(rem);
        const int off = q * BQ_BYTES + oc * A_STRIDE + cs * 8;
        *(ull*)(Bhi + off) = ph;
        *(ull*)(Blo + off) = pl;
    }
    __syncthreads();

    const int wid = tid >> 5, lane = tid & 31;
    const int g = lane >> 2, t = lane & 3;

    float acc[2][4][4];
    #pragma unroll
    for (int m = 0; m < 2; m++)
        #pragma unroll
        for (int nt = 0; nt < 4; nt++)
            #pragma unroll
            for (int r = 0; r < 4; r++) acc[m][nt][r] = 0.0f;

    const int mt0 = wid, mt1 = wid + 8;

    #pragma unroll
    for (int q = 0; q < 4; q++) {
        const int r0 = (q >> 1) * 16 + (q & 1);
        const char* Bq_hi = Bhi + q * BQ_BYTES;
        const char* Bq_lo = Blo + q * BQ_BYTES;
        const int arow0 = (mt0 * 16 + r0 + g) * A_STRIDE;
        const int arow1 = (mt1 * 16 + r0 + g) * A_STRIDE;

        #pragma unroll
        for (int ks = 0; ks < 4; ks++) {
            const int co = ks * 32 + t * 4;
            u32 ahi[2][4], alo[2][4], bhi[4][2], blo[4][2];
            #pragma unroll
            for (int m = 0; m < 2; m++) {
                const int rb = (m ? arow1 : arow0) + co;
                ahi[m][0] = *(const u32*)(Ahi + rb);
                ahi[m][1] = *(const u32*)(Ahi + rb + 8 * A_STRIDE);
                ahi[m][2] = *(const u32*)(Ahi + rb + 16);
                ahi[m][3] = *(const u32*)(Ahi + rb + 8 * A_STRIDE + 16);
                alo[m][0] = *(const u32*)(Alo + rb);
                alo[m][1] = *(const u32*)(Alo + rb + 8 * A_STRIDE);
                alo[m][2] = *(const u32*)(Alo + rb + 16);
                alo[m][3] = *(const u32*)(Alo + rb + 8 * A_STRIDE + 16);
            }
            #pragma unroll
            for (int nt = 0; nt < 4; nt++) {
                const int bo = (nt * 8 + g) * A_STRIDE + co;
                bhi[nt][0] = *(const u32*)(Bq_hi + bo);
                bhi[nt][1] = *(const u32*)(Bq_hi + bo + 16);
                blo[nt][0] = *(const u32*)(Bq_lo + bo);
                blo[nt][1] = *(const u32*)(Bq_lo + bo + 16);
            }
            #pragma unroll
            for (int m = 0; m < 2; m++)
                #pragma unroll
                for (int nt = 0; nt < 4; nt++) {
                    mma16816(acc[m][nt], ahi[m], bhi[nt]);
                    mma16816(acc[m][nt], alo[m], bhi[nt]);
                    mma16816(acc[m][nt], ahi[m], blo[nt]);
                }
        }
    }

    float* ob = out + (size_t)n * 7200;
    #pragma unroll
    for (int m = 0; m < 2; m++) {
        const int mt = m ? mt1 : mt0;
        const int r1 = mt * 16 + g;
        const int r2 = r1 + 8;
        const int oh1 = r1 >> 4, ow1 = r1 & 15;
        const int oh2 = r2 >> 4, ow2 = r2 & 15;
        #pragma unroll
        for (int nt = 0; nt < 4; nt++) {
            const int c0 = nt * 8 + 2 * t;
            const float b0 = sbias[c0], b1 = sbias[c0 + 1];
            if (oh1 < 15 && ow1 < 15) {
                float v0 = acc[m][nt][0] + b0;
                float v1 = acc[m][nt][1] + b1;
                ob[c0 * 225 + oh1 * 15 + ow1] = v0 > 0.0f ? v0 : 0.0f;
                ob[(c0 + 1) * 225 + oh1 * 15 + ow1] = v1 > 0.0f ? v1 : 0.0f;
            }
            if (oh2 < 15 && ow2 < 15) {
                float v2 = acc[m][nt][2] + b0;
                float v3 = acc[m][nt][3] + b1;
                ob[c0 * 225 + oh2 * 15 + ow2] = v2 > 0.0f ? v2 : 0.0f;
                ob[(c0 + 1) * 225 + oh2 * 15 + ow2] = v3 > 0.0f ? v3 : 0.0f;
            }
        }
    }
}

// ===========================================================================
// conv2 via mma.sync (bf16x3): k=4 s=2 conv == 2x2 stride-1 conv over 128
// phase channels (32ic x 2s x 2p) on an 8x8 phase grid. CTA = 2 images.
// A: 144 rows x 128ch (272B stride), hi/lo. B: per-phase (dh) 2 quadrants.
// Quadrant q=(dh,dw) -> A-row offset dh*8+dw; out(oh,ow) = D[im*64+oh*8+ow].
// ===========================================================================
#define C2_STRIDE  272
#define C2_A_SZ    (144 * C2_STRIDE)     // 39168
#define C2_B_SZ    (128 * C2_STRIDE)     // 34816
#define C2_OFF_AHI 512
#define C2_OFF_ALO (C2_OFF_AHI + C2_A_SZ)
#define C2_OFF_BHI (C2_OFF_ALO + C2_A_SZ)
#define C2_OFF_BLO (C2_OFF_BHI + C2_B_SZ)
#define C2_SMEM    (C2_OFF_BLO + C2_B_SZ)   // 148480

__global__ __launch_bounds__(256, 1)
void conv2_mma_kernel(const float* __restrict__ in, const float* __restrict__ w,
                      const float* __restrict__ bias, float* __restrict__ out)
{
    extern __shared__ __align__(16) char smem[];
    float* sbias = (float*)smem;
    char* Ahi = smem + C2_OFF_AHI;
    char* Alo = smem + C2_OFF_ALO;
    char* Bhi = smem + C2_OFF_BHI;
    char* Blo = smem + C2_OFF_BLO;

    const int tid = threadIdx.x;
    const int nb = blockIdx.x * 2;

    if (tid < 64) sbias[tid] = bias[tid];

    // ---- A: X'[im*64 + gh*8+gw][c*4 + s*2 + p] = in[n][c][2gh+s][2gw+p] ----
    for (int idx = tid; idx < 4096; idx += 256) {
        const int im = idx >> 11;
        const int rc = idx & 2047;
        const int c  = rc >> 6;
        const int r  = rc & 63;
        const int gh = r >> 3, gw = r & 7;
        const float* ip = in + (size_t)((nb + im) * 32 + c) * 225;
        float4 v;
        {
            const int ih0 = 2 * gh, iw0 = 2 * gw;
            v.x = in[0]; // placeholder overwritten below
            v.x = (ih0 < 15 && iw0     < 15) ? ip[ih0 * 15 + iw0]     : 0.0f;
            v.y = (ih0 < 15 && iw0 + 1 < 15) ? ip[ih0 * 15 + iw0 + 1] : 0.0f;
            v.z = (ih0 + 1 < 15 && iw0     < 15) ? ip[(ih0 + 1) * 15 + iw0]     : 0.0f;
            v.w = (ih0 + 1 < 15 && iw0 + 1 < 15) ? ip[(ih0 + 1) * 15 + iw0 + 1] : 0.0f;
        }
        float4 rem;
        const ull ph = pack_hi4(v, &rem);
        const ull pl = pack_lo4(rem);
        const int off = (im * 64 + r) * C2_STRIDE + c * 8;
        *(ull*)(Ahi + off) = ph;
        *(ull*)(Alo + off) = pl;
    }
    // zero pad rows 128..143 (first 256 bytes of each row matter)
    for (int i = tid; i < 1024; i += 256) {
        const int half = i >> 9;
        const int j = i & 511;
        const int off = (128 + (j >> 5)) * C2_STRIDE + (j & 31) * 8;
        *(ull*)((half ? Alo : Ahi) + off) = 0ull;
    }

    const int wid = tid >> 5, lane = tid & 31;
    const int g = lane >> 2, t = lane & 3;

    float acc[8][4];
    #pragma unroll
    for (int nt = 0; nt < 8; nt++)
        #pragma unroll
        for (int r = 0; r < 4; r++) acc[nt][r] = 0.0f;

    // ---- two phases over dh ----
    for (int dh = 0; dh < 2; dh++) {
        __syncthreads();   // previous-phase B consumers done
        // B: Wq[dw*64 + oc][c*4 + s*2 + p] = w[oc][c][2dh+s][2dw+p]
        for (int idx = tid; idx < 4096; idx += 256) {
            const int dw = idx >> 11;
            const int oc_c = idx & 2047;
            const int oc = oc_c >> 5;
            const int c = oc_c & 31;
            const float* wp = w + (size_t)(oc * 32 + c) * 16;
            float4 v;
            v.x = wp[(2 * dh) * 4 + 2 * dw];
            v.y = wp[(2 * dh) * 4 + 2 * dw + 1];
            v.z = wp[(2 * dh + 1) * 4 + 2 * dw];
            v.w = wp[(2 * dh + 1) * 4 + 2 * dw + 1];
            float4 rem;
            const ull ph = pack_hi4(v, &rem);
            const ull pl = pack_lo4(rem);
            const int off = (dw * 64 + oc) * C2_STRIDE + c * 8;
            *(ull*)(Bhi + off) = ph;
            *(ull*)(Blo + off) = pl;
        }
        __syncthreads();

        #pragma unroll
        for (int ql = 0; ql < 2; ql++) {
            const int roff = dh * 8 + ql;
            const char* Bq_hi = Bhi + ql * 64 * C2_STRIDE;
            const char* Bq_lo = Blo + ql * 64 * C2_STRIDE;
            const int arow = (wid * 16 + roff + g) * C2_STRIDE;

            #pragma unroll
            for (int ks = 0; ks < 8; ks++) {
                const int co = ks * 32 + t * 4;
                u32 ahi[4], alo[4], bhi[8][2], blo[8][2];
                const int rb = arow + co;
                ahi[0] = *(const u32*)(Ahi + rb);
                ahi[1] = *(const u32*)(Ahi + rb + 8 * C2_STRIDE);
                ahi[2] = *(const u32*)(Ahi + rb + 16);
                ahi[3] = *(const u32*)(Ahi + rb + 8 * C2_STRIDE + 16);
                alo[0] = *(const u32*)(Alo + rb);
                alo[1] = *(const u32*)(Alo + rb + 8 * C2_STRIDE);
                alo[2] = *(const u32*)(Alo + rb + 16);
                alo[3] = *(const u32*)(Alo + rb + 8 * C2_STRIDE + 16);
                #pragma unroll
                for (int nt = 0; nt < 8; nt++) {
                    const int bo = (nt * 8 + g) * C2_STRIDE + co;
                    bhi[nt][0] = *(const u32*)(Bq_hi + bo);
                    bhi[nt][1] = *(const u32*)(Bq_hi + bo + 16);
                    blo[nt][0] = *(const u32*)(Bq_lo + bo);
                    blo[nt][1] = *(const u32*)(Bq_lo + bo + 16);
                }
                #pragma unroll
                for (int nt = 0; nt < 8; nt++) {
                    mma16816(acc[nt], ahi, bhi[nt]);
                    mma16816(acc[nt], alo, bhi[nt]);
                    mma16816(acc[nt], ahi, blo[nt]);
                }
            }
        }
    }

    // ---- epilogue: D[im*64 + oh*8 + ow][oc] -> out (n,64,6,6) ----
    #pragma unroll
    for (int half = 0; half < 2; half++) {
        const int r = wid * 16 + g + half * 8;
        const int im = r >> 6;
        const int rl = r & 63;
        const int oh = rl >> 3, ow = rl & 7;
        if (oh < 6 && ow < 6) {
            float* ob = out + (size_t)(nb + im) * 2304 + oh * 6 + ow;
            #pragma unroll
            for (int nt = 0; nt < 8; nt++) {
                const int oc = nt * 8 + 2 * t;
                float v0 = acc[nt][half * 2]     + sbias[oc];
                float v1 = acc[nt][half * 2 + 1] + sbias[oc + 1];
                ob[oc * 36]       = v0 > 0.0f ? v0 : 0.0f;
                ob[(oc + 1) * 36] = v1 > 0.0f ? v1 : 0.0f;
            }
        }
    }
}

// ===========================================================================
// conv3 (scalar): in (n,64,6,6) -> relu -> flatten (n, 1024), k=3 s=1
// ===========================================================================
__global__ __launch_bounds__(128, 2)
void conv3_kernel(const float* __restrict__ in, const float* __restrict__ w,
                  const float* __restrict__ bias, float* __restrict__ out)
{
    extern __shared__ float sm[];
    float* img = sm;
    float* wk  = sm + 9216;

    const int tid = threadIdx.x;
    const int nbase = (blockIdx.x >> 1) * 4;
    const int oc0base = (blockIdx.x & 1) * 32;

    const float4* ip = (const float4*)(in + (size_t)nbase * 2304);
    for (int i = tid; i < 2304; i += 128) ((float4*)img)[i] = ip[i];
    for (int e = tid; e < 18432; e += 128) {
        int ocl = e / 576, rr = e - ocl * 576;
        wk[ocl * 577 + rr] = w[(oc0base + ocl) * 576 + rr];
    }
    __syncthreads();

    const int im = tid >> 5;
    const int r  = tid & 31;
    const int ocg = r & 7, oh = r >> 3;
    const int oc0 = ocg * 4;

    float acc[4][4];
    #pragma unroll
    for (int i = 0; i < 4; i++)
        #pragma unroll
        for (int j = 0; j < 4; j++) acc[i][j] = 0.0f;

    const float* ibase = img + im * 2304 + oh * 6;
    for (int ic = 0; ic < 64; ic++) {
        const float* ib = ibase + ic * 36;
        const float* wb = wk + ic * 9;
        #pragma unroll
        for (int kh = 0; kh < 3; kh++) {
            #pragma unroll
            for (int kw = 0; kw < 3; kw++) {
                const float x0 = ib[kh * 6 + kw];
                const float x1 = ib[kh * 6 + kw + 1];
                const float x2 = ib[kh * 6 + kw + 2];
                const float x3 = ib[kh * 6 + kw + 3];
                #pragma unroll
                for (int i = 0; i < 4; i++) {
                    const float wv = wb[(oc0 + i) * 577 + kh * 3 + kw];
                    acc[i][0] += wv * x0;
                    acc[i][1] += wv * x1;
                    acc[i][2] += wv * x2;
                    acc[i][3] += wv * x3;
                }
            }
        }
    }
    const int n = nbase + im;
    #pragma unroll
    for (int i = 0; i < 4; i++) {
        const int oc = oc0base + oc0 + i;
        const float bi = bias[oc];
        #pragma unroll
        for (int j = 0; j < 4; j++) {
            float v = acc[i][j] + bi;
            out[(size_t)n * 1024 + oc * 16 + oh * 4 + j] = v > 0.0f ? v : 0.0f;
        }
    }
}

// ===========================================================================
// GEMM (NT) via mma.sync bf16x3: C[M,N] = act(A[M,K]*B[N,K]^T + b1 (+b2))
// CTA tile 128x64, 8 warps (4m x 2n), warp tile 32x32, BK=32.
// smem rows: 32 bf16 = 64B + 16 pad = 80B stride -> conflict-free fragments.
// Requires M%128==0, N%64==0, K%32==0.
// ===========================================================================
template <bool RELU>
__global__ __launch_bounds__(256, 2)
void gemm_hmma(const float* __restrict__ A, const float* __restrict__ B,
               const float* __restrict__ b1, const float* __restrict__ b2,
               float* __restrict__ C, int K, int N)
{
    __shared__ __align__(16) char Ahi[128 * 80];
    __shared__ __align__(16) char Alo[128 * 80];
    __shared__ __align__(16) char Bhi[64 * 80];
    __shared__ __align__(16) char Blo[64 * 80];

    const int tid = threadIdx.x;
    const int m0 = blockIdx.y * 128;
    const int n0 = blockIdx.x * 64;
    const int wid = tid >> 5, lane = tid & 31;
    const int g = lane >> 2, t = lane & 3;
    const int wm = wid & 3;        // m offset wm*32
    const int wn = wid >> 2;       // n offset wn*32

    float acc[2][4][4];
    #pragma unroll
    for (int ms = 0; ms < 2; ms++)
        #pragma unroll
        for (int nt = 0; nt < 4; nt++)
            #pragma unroll
            for (int r = 0; r < 4; r++) acc[ms][nt][r] = 0.0f;

    for (int k0 = 0; k0 < K; k0 += 32) {
        // load + convert chunk
        #pragma unroll
        for (int l = 0; l < 4; l++) {
            const int idx = tid + l * 256;         // 0..1023
            const int row = idx >> 3;
            const int c8 = (idx & 7) * 8;          // byte offset of 4-elem group
            float4 v = *(const float4*)(A + (size_t)(m0 + row) * K + k0 + (idx & 7) * 4);
            float4 rem;
            const ull ph = pack_hi4(v, &rem);
            const ull pl = pack_lo4(rem);
            *(ull*)(Ahi + row * 80 + c8) = ph;
            *(ull*)(Alo + row * 80 + c8) = pl;
        }
        #pragma unroll
        for (int l = 0; l < 2; l++) {
            const int idx = tid + l * 256;         // 0..511
            const int row = idx >> 3;
            const int c8 = (idx & 7) * 8;
            float4 v = *(const float4*)(B + (size_t)(n0 + row) * K + k0 + (idx & 7) * 4);
            float4 rem;
            const ull ph = pack_hi4(v, &rem);
            const ull pl = pack_lo4(rem);
            *(ull*)(Bhi + row * 80 + c8) = ph;
            *(ull*)(Blo + row * 80 + c8) = pl;
        }
        __syncthreads();

        #pragma unroll
        for (int ks = 0; ks < 2; ks++) {
            const int co = ks * 32 + t * 4;
            u32 ahi[2][4], alo[2][4], bhi[4][2], blo[4][2];
            #pragma unroll
            for (int ms = 0; ms < 2; ms++) {
                const int rb = (wm * 32 + ms * 16 + g) * 80 + co;
                ahi[ms][0] = *(const u32*)(Ahi + rb);
                ahi[ms][1] = *(const u32*)(Ahi + rb + 8 * 80);
                ahi[ms][2] = *(const u32*)(Ahi + rb + 16);
                ahi[ms][3] = *(const u32*)(Ahi + rb + 8 * 80 + 16);
                alo[ms][0] = *(const u32*)(Alo + rb);
                alo[ms][1] = *(const u32*)(Alo + rb + 8 * 80);
                alo[ms][2] = *(const u32*)(Alo + rb + 16);
                alo[ms][3] = *(const u32*)(Alo + rb + 8 * 80 + 16);
            }
            #pragma unroll
            for (int nt = 0; nt < 4; nt++) {
                const int bo = (wn * 32 + nt * 8 + g) * 80 + co;
                bhi[nt][0] = *(const u32*)(Bhi + bo);
                bhi[nt][1] = *(const u32*)(Bhi + bo + 16);
                blo[nt][0] = *(const u32*)(Blo + bo);
                blo[nt][1] = *(const u32*)(Blo + bo + 16);
            }
            #pragma unroll
            for (int ms = 0; ms < 2; ms++)
                #pragma unroll
                for (int nt = 0; nt < 4; nt++) {
                    mma16816(acc[ms][nt], ahi[ms], bhi[nt]);
                    mma16816(acc[ms][nt], alo[ms], bhi[nt]);
                    mma16816(acc[ms][nt], ahi[ms], blo[nt]);
                }
        }
        __syncthreads();
    }

    // epilogue
    #pragma unroll
    for (int ms = 0; ms < 2; ms++) {
        #pragma unroll
        for (int half = 0; half < 2; half++) {
            const int row = m0 + wm * 32 + ms * 16 + g + half * 8;
            #pragma unroll
            for (int nt = 0; nt < 4; nt++) {
                const int col = n0 + wn * 32 + nt * 8 + 2 * t;
                float bb0 = b1[col]     + (b2 ? b2[col]     : 0.0f);
                float bb1 = b1[col + 1] + (b2 ? b2[col + 1] : 0.0f);
                float v0 = acc[ms][nt][half * 2]     + bb0;
                float v1 = acc[ms][nt][half * 2 + 1] + bb1;
                if (RELU) { v0 = v0 > 0.0f ? v0 : 0.0f; v1 = v1 > 0.0f ? v1 : 0.0f; }
                C[(size_t)row * N + col]     = v0;
                C[(size_t)row * N + col + 1] = v1;
            }
        }
    }
}

// ===========================================================================
// LSTM (R2): 64 blocks x 256 threads
// ===========================================================================
__global__ __launch_bounds__(256, 1)
void lstm_kernel(const float* __restrict__ gx, const float* __restrict__ whh,
                 const int* __restrict__ done,
                 const float* __restrict__ h0, const float* __restrict__ c0,
                 float* __restrict__ out)
{
    extern __shared__ float sm[];
    float* ws     = sm;
    float* h_s    = sm + 16 * 264;
    float* gate_s = h_s + 32 * 264;
    float* c_s    = gate_s + 512;

    const int tid = threadIdx.x;
    const int j0 = blockIdx.x * 4;

    #pragma unroll
    for (int l = 0; l < 4; l++) {
        const int id = tid + l * 256;
        const int r = id >> 6;
        const int c4 = (id & 63) * 4;
        const int g = r >> 2, jj = r & 3;
        *(float4*)(ws + r * 264 + c4) =
            *(const float4*)(whh + (size_t)(g * 256 + j0 + jj) * 256 + c4);
    }
    if (tid < 128) {
        const int b = tid >> 2, jj = tid & 3;
        c_s[tid] = c0[b * 256 + j0 + jj];
    }
    unsigned bar_gen = 0;
    if (tid == 0) bar_gen = *((volatile unsigned*)&g_gen);
    __syncthreads();

    const int u = tid & 7;
    const int b = tid >> 3;
    const int jj = u & 3, gh = u >> 2;
    const float* w0 = ws + ((2 * gh) * 4 + jj) * 264;
    const float* w1 = ws + ((2 * gh + 1) * 4 + jj) * 264;
    const float* hb = h_s + b * 264;

    for (int t = 0; t < 64; t++) {
        const float* hsrc = (t == 0) ? h0 : g_hbuf[(t - 1) & 1];
        const int* dn = done + t * 32;
        #pragma unroll
        for (int l = 0; l < 8; l++) {
            const int f = tid + l * 256;
            const int bb = f >> 6;
            const int kc = (f & 63) * 4;
            const float m = 1.0f - (float)dn[bb];
            float4 v = *(const float4*)(hsrc + bb * 256 + kc);
            v.x *= m; v.y *= m; v.z *= m; v.w *= m;
            *(float4*)(h_s + bb * 264 + kc) = v;
        }
        __syncthreads();

        float s00 = 0, s01 = 0, s02 = 0, s03 = 0;
        float s10 = 0, s11 = 0, s12 = 0, s13 = 0;
        #pragma unroll 8
        for (int k = 0; k < 256; k += 4) {
            const float4 h4 = *(const float4*)(hb + k);
            const float4 wa = *(const float4*)(w0 + k);
            const float4 wb4 = *(const float4*)(w1 + k);
            s00 += h4.x * wa.x;  s01 += h4.y * wa.y;
            s02 += h4.z * wa.z;  s03 += h4.w * wa.w;
            s10 += h4.x * wb4.x; s11 += h4.y * wb4.y;
            s12 += h4.z * wb4.z; s13 += h4.w * wb4.w;
        }
        const int row = t * 32 + b;
        const float g0v = ((s00 + s01) + (s02 + s03)) +
                          gx[(size_t)row * 1024 + (2 * gh) * 256 + j0 + jj];
        const float g1v = ((s10 + s11) + (s12 + s13)) +
                          gx[(size_t)row * 1024 + (2 * gh + 1) * 256 + j0 + jj];
        gate_s[(b * 4 + jj) * 4 + 2 * gh] = g0v;
        gate_s[(b * 4 + jj) * 4 + 2 * gh + 1] = g1v;
        __syncthreads();

        if (tid < 128) {
            const int bb = tid >> 2, j2 = tid & 3;
            const float* gp = gate_s + tid * 4;
            const float gi = gp[0], gf = gp[1], gg = gp[2], go = gp[3];
            const float m = 1.0f - (float)dn[bb];
            const float cold = c_s[tid] * m;
            const float si = 1.0f / (1.0f + __expf(-gi));
            const float sf = 1.0f / (1.0f + __expf(-gf));
            const float so = 1.0f / (1.0f + __expf(-go));
            const float cn = sf * cold + si * tanhf(gg);
            const float h = so * tanhf(cn);
            c_s[tid] = cn;
            const int j = j0 + j2;
            g_hbuf[t & 1][bb * 256 + j] = h;
            out[(size_t)(t * 32 + bb) * 256 + j] = h;
        }
        __threadfence();
        __syncthreads();

        if (t < 63) {
            if (tid == 0) {
                const unsigned prev = atomicAdd(&g_count, 1);
                if (prev == gridDim.x - 1) {
                    g_count = 0;
                    __threadfence();
                    atomicAdd(&g_gen, 1);
                } else {
                    while (*((volatile unsigned*)&g_gen) == bar_gen) { }
                }
                bar_gen++;
                __threadfence();
            }
            __syncthreads();
        }
    }
}

// ===========================================================================
extern "C" void kernel_launch(void* const* d_in, const int* in_sizes, int n_in,
                              void* d_out, int out_size)
{
    const float* x    = (const float*)d_in[0];
    const int*   done = (const int*)d_in[1];
    const float* w1   = (const float*)d_in[2];
    const float* b1   = (const float*)d_in[3];
    const float* w2   = (const float*)d_in[4];
    const float* b2   = (const float*)d_in[5];
    const float* w3   = (const float*)d_in[6];
    const float* b3   = (const float*)d_in[7];
    const float* fcw  = (const float*)d_in[8];
    const float* fcb  = (const float*)d_in[9];
    const float* wih  = (const float*)d_in[10];
    const float* whh  = (const float*)d_in[11];
    const float* bih  = (const float*)d_in[12];
    const float* bhh  = (const float*)d_in[13];
    const float* h0   = (const float*)d_in[14];
    const float* c0   = (const float*)d_in[15];
    float* out = (float*)d_out;

    float *buf1, *buf2, *buf3, *feats, *gatesx;
    cudaGetSymbolAddress((void**)&buf1,   g_buf1);
    cudaGetSymbolAddress((void**)&buf2,   g_buf2);
    cudaGetSymbolAddress((void**)&buf3,   g_buf3);
    cudaGetSymbolAddress((void**)&feats,  g_feats);
    cudaGetSymbolAddress((void**)&gatesx, g_gatesx);

    cudaFuncSetAttribute(conv1_mma_kernel, cudaFuncAttributeMaxDynamicSharedMemorySize, C1_SMEM);
    cudaFuncSetAttribute(conv2_mma_kernel, cudaFuncAttributeMaxDynamicSharedMemorySize, C2_SMEM);
    cudaFuncSetAttribute(conv3_kernel, cudaFuncAttributeMaxDynamicSharedMemorySize, SMEM3);
    cudaFuncSetAttribute(lstm_kernel,  cudaFuncAttributeMaxDynamicSharedMemorySize, SMEML);

    conv1_mma_kernel<<<2048, 256, C1_SMEM>>>(x, w1, b1, buf1);
    conv2_mma_kernel<<<1024, 256, C2_SMEM>>>(buf1, w2, b2, buf2);
    conv3_kernel<<<1024, 128, SMEM3>>>(buf2, w3, b3, buf3);
    gemm_hmma<true><<<dim3(8, 16), 256>>>(buf3, fcw, fcb, nullptr, feats, 1024, 512);
    gemm_hmma<false><<<dim3(16, 16), 256>>>(feats, wih, bih, bhh, gatesx, 512, 1024);
    lstm_kernel<<<64, 256, SMEML>>>(gatesx, whh, done, h0, c0, out);
}